// round 10
// baseline (speedup 1.0000x reference)
#include <cuda_runtime.h>
#include <math.h>

#define B_  8
#define C_  12
#define S_  784
#define NTOK 785
#define D_  768
#define HH  28
#define PATCH 84
#define GCNH 512

#define ROWF4    192u          /* 768 floats per row */
#define BATF4    150720u       /* 785*192 per batch  */
#define NHS4     1205760u      /* 8*785*192          */
#define NCHUNK   588u          /* (8*784*192)/2048   */
#define CH_P1    400u
#define CH_P2    150u          /* P3 gets the last 38 */

// ---------------- scratch (no allocation allowed) ----------------
__device__ float         g_amap[B_*C_*S_];
__device__ unsigned char g_selflag[B_*C_*S_];
__device__ float         g_wk[B_*GCNH];
__device__ int           g_pidx[B_*S_];
__device__ int           g_key[B_*S_];

// ---------------- software grid barrier ----------------
__device__ unsigned g_gen = 0;
__device__ unsigned g_cnt = 0;

__device__ __forceinline__ void gridSync(unsigned nblk) {
    __syncthreads();
    if (threadIdx.x == 0) {
        volatile unsigned* vgen = &g_gen;
        unsigned my_gen = *vgen;                 // read gen BEFORE arriving
        __threadfence();                         // release prior writes
        if (atomicAdd(&g_cnt, 1u) == nblk - 1u) {
            g_cnt = 0;
            __threadfence();
            *vgen = my_gen + 1u;                 // release
        } else {
            while (*vgen == my_gen) { __nanosleep(64); }
        }
        __threadfence();                         // acquire
    }
    __syncthreads();
}

// monotone float->uint: a > b <=> f2u(a) > f2u(b)
__device__ __forceinline__ unsigned f2u(float f) {
    unsigned u = __float_as_uint(f);
    return (u & 0x80000000u) ? ~u : (u | 0x80000000u);
}

// ---------------- shared memory union ----------------
struct SmemSel {
    float    sc[S_];
    unsigned key[S_];
    int      hist[256];
    int      wtot[8];
    unsigned prefix;
    int      k;
};
struct SmemKB {
    float    pw[S_];
    float    binm[S_];
    float    cnt[S_];
    float    wsum[8];
    unsigned long long wkey[8];
    float4   wq[8];
    float    mean, panchor;
    float4   q;
    int      anchor;
};
struct SmemMV { float wk[GCNH]; float partr[256]; };
struct SmemRk { int kk[S_]; };
union SmemAll { SmemSel sel; SmemKB kb; SmemMV mv; SmemRk rk; };

// ---- bulk copy of rows 1..784 (chunk = 2048 float4, ILP=8) ------------------
__device__ __forceinline__ void copy8(const float4* __restrict__ in4,
                                      float4* __restrict__ out4, unsigned chunk) {
    unsigned m0 = chunk * 2048u + threadIdx.x;
    unsigned src[8]; float4 v[8];
    #pragma unroll
    for (int e = 0; e < 8; e++) {
        unsigned m = m0 + (unsigned)e * 256u;       // m in [0, 8*784*192)
        unsigned b = m / 150528u;                   // 784*192 per batch
        src[e] = m + (b + 1u) * ROWF4;              // skip row 0 of each batch
    }
    #pragma unroll
    for (int e = 0; e < 8; e++) v[e] = in4[src[e]];
    #pragma unroll
    for (int e = 0; e < 8; e++) out4[src[e]] = v[e];
}

// ---- radix top-84 select for one (b,c) --------------------------------------
__device__ void doSelect(SmemSel& sm, const float* __restrict__ x, int bc) {
    int t = threadIdx.x;
    unsigned lane = t & 31;
    int wid = t >> 5;
    const float* base = x + (size_t)bc * NTOK * NTOK + 1;   // x[b,c,0,1:]
    for (int s = t; s < S_; s += 256) {
        float v = base[s];
        sm.sc[s]  = v;
        sm.key[s] = f2u(v);
    }
    if (t == 0) { sm.prefix = 0u; sm.k = PATCH; }

    #pragma unroll
    for (int p = 0; p < 4; p++) {
        int shift = 24 - 8 * p;
        sm.hist[t] = 0;
        __syncthreads();
        unsigned pref = sm.prefix;
        int      k    = sm.k;
        for (int s = t; s < S_; s += 256) {
            unsigned kk = sm.key[s];
            bool cand = (p == 0) || (((kk ^ pref) >> (shift + 8)) == 0u);
            if (cand) atomicAdd(&sm.hist[(kk >> shift) & 255], 1);
        }
        __syncthreads();
        int v = sm.hist[t];
        int xsum = v;
        #pragma unroll
        for (int off = 1; off < 32; off <<= 1) {
            int y = __shfl_down_sync(0xFFFFFFFFu, xsum, off);
            if (lane + off < 32) xsum += y;
        }
        if (lane == 0) sm.wtot[wid] = xsum;
        __syncthreads();
        int addhi = 0;
        for (int ww = wid + 1; ww < 8; ww++) addhi += sm.wtot[ww];
        int suffix = xsum + addhi;
        int above  = suffix - v;
        if (suffix >= k && above < k) {        // exactly one thread matches
            sm.prefix = pref | ((unsigned)t << shift);
            sm.k      = k - above;
        }
    }
    __syncthreads();

    unsigned T  = sm.prefix;
    int     neq = sm.k;
    for (int s = t; s < S_; s += 256) {
        unsigned kk = sm.key[s];
        bool sel;
        if (kk > T) sel = true;
        else if (kk == T) {
            int eq = 0;
            for (int u = 0; u < s; u++) eq += (sm.key[u] == T);
            sel = eq < neq;
        } else sel = false;
        float v = sm.sc[s];
        g_amap[bc*S_ + s]    = sel ? v : 0.7f * v;
        g_selflag[bc*S_ + s] = sel ? 1 : 0;
    }
}

// ---- per-batch analytics (rank-1 GCN collapse) ------------------------------
__device__ void doKB(SmemKB& sm, const float* __restrict__ w1, int b) {
    int t = threadIdx.x;
    unsigned lane = t & 31;
    int wid = t >> 5;
    const int NT = 256;

    float part = 0.f;
    for (int s = t; s < S_; s += NT) {
        float smv = 0.f;
        #pragma unroll
        for (int c = 0; c < C_; c++) smv += g_amap[(b*C_ + c)*S_ + s];
        sm.binm[s] = smv;
        sm.pw[s]   = smv * (1.f/12.f);
        part += smv;
    }
    #pragma unroll
    for (int off = 16; off > 0; off >>= 1) part += __shfl_down_sync(0xFFFFFFFFu, part, off);
    if (lane == 0) sm.wsum[wid] = part;
    __syncthreads();
    if (t < 8) {
        float v = sm.wsum[t];
        #pragma unroll
        for (int off = 4; off > 0; off >>= 1) v += __shfl_down_sync(0xFFu, v, off);
        if (t == 0) sm.mean = v / (float)S_;
    }
    __syncthreads();
    float mean = sm.mean;
    for (int s = t; s < S_; s += NT) sm.binm[s] = (sm.binm[s] > mean) ? 1.f : 0.f;

    // anchor = argmax binm*pw (first index wins), u64 key, -0.0 canonicalized
    unsigned long long akey = 0ull;
    for (int s = t; s < S_; s += NT) {
        float v = sm.binm[s] * sm.pw[s];
        unsigned uv = __float_as_uint(v);
        if (uv == 0x80000000u) uv = 0u;
        unsigned fv = (uv & 0x80000000u) ? ~uv : (uv | 0x80000000u);
        unsigned long long k = ((unsigned long long)fv << 32) | (unsigned long long)(0xFFFFFFFFu - (unsigned)s);
        if (k > akey) akey = k;
    }
    #pragma unroll
    for (int off = 16; off > 0; off >>= 1) {
        unsigned long long o = __shfl_down_sync(0xFFFFFFFFu, akey, off);
        if (o > akey) akey = o;
    }
    if (lane == 0) sm.wkey[wid] = akey;
    __syncthreads();
    if (t < 8) {
        unsigned long long k = sm.wkey[t];
        #pragma unroll
        for (int off = 4; off > 0; off >>= 1) {
            unsigned long long o = __shfl_down_sync(0xFFu, k, off);
            if (o > k) k = o;
        }
        if (t == 0) {
            int a = (int)(0xFFFFFFFFu - (unsigned)(k & 0xFFFFFFFFull));
            sm.anchor = a;
            sm.panchor = sm.pw[a];
        }
    }
    __syncthreads();
    int anchor = sm.anchor;
    float ai = (float)(anchor / HH), aj = (float)(anchor % HH);

    float4 acc4 = make_float4(0.f, 0.f, 0.f, 0.f);
    for (int s = t; s < S_; s += NT) {
        float rx = ((float)(s / HH) - ai) / 28.0f;
        float ry = ((float)(s % HH) - aj) / 28.0f;
        float dist = sqrtf(rx*rx + ry*ry);
        float ang  = (atan2f(ry, rx) / (float)M_PI + 1.f) * 0.5f;
        float p = sm.pw[s];
        acc4.x += p * dist;
        acc4.y += p * ang;
        if (p > 0.f) acc4.z += p*p; else if (p < 0.f) acc4.w += p*p;
    }
    #pragma unroll
    for (int off = 16; off > 0; off >>= 1) {
        acc4.x += __shfl_down_sync(0xFFFFFFFFu, acc4.x, off);
        acc4.y += __shfl_down_sync(0xFFFFFFFFu, acc4.y, off);
        acc4.z += __shfl_down_sync(0xFFFFFFFFu, acc4.z, off);
        acc4.w += __shfl_down_sync(0xFFFFFFFFu, acc4.w, off);
    }
    if (lane == 0) sm.wq[wid] = acc4;
    __syncthreads();
    if (t < 8) {
        float4 a = sm.wq[t];
        #pragma unroll
        for (int off = 4; off > 0; off >>= 1) {
            a.x += __shfl_down_sync(0xFFu, a.x, off);
            a.y += __shfl_down_sync(0xFFu, a.y, off);
            a.z += __shfl_down_sync(0xFFu, a.z, off);
            a.w += __shfl_down_sync(0xFFu, a.w, off);
        }
        if (t == 0) sm.q = a;
    }
    __syncthreads();
    float Q0 = sm.q.x, Q1 = sm.q.y, AP = sm.q.z, AM = sm.q.w;
    float pa = sm.panchor;

    for (int k = t; k < GCNH; k += NT) {
        float v = Q0 * w1[k] + Q1 * w1[GCNH + k];
        float wv = (v > 0.f) ? v * AP : ((v < 0.f) ? v * AM : 0.f);
        g_wk[b*GCNH + k] = pa * wv;
    }

    for (int s = t; s < S_; s += NT) {
        int c = 0;
        #pragma unroll
        for (int ch = 0; ch < C_; ch++) c += g_selflag[(b*C_ + ch)*S_ + s];
        sm.cnt[s] = (float)c;
    }
    __syncthreads();
    for (int s = t; s < S_; s += NT) {
        int li = s / HH, lj = s % HH;
        float acc = 0.f;
        #pragma unroll
        for (int di = -1; di <= 1; di++) {
            #pragma unroll
            for (int dj = -1; dj <= 1; dj++) {
                int ni = li + di, nj = lj + dj;
                if (ni >= 0 && ni < HH && nj >= 0 && nj < HH) {
                    float kw = ((di == 0) ? 2.f : 1.f) * ((dj == 0) ? 2.f : 1.f);
                    acc += kw * sm.cnt[ni*HH + nj];
                }
            }
        }
        g_key[b*S_ + s] = (int)acc * 1024 + (1023 - s);
    }
}

// ---------------- the single fused kernel (4 blocks/SM) ----------------
__global__ void __launch_bounds__(256, 4)
kAll(const float* __restrict__ x, const float* __restrict__ w1,
     const float* __restrict__ w2, const float* __restrict__ hsf,
     const float4* __restrict__ in4, float4* __restrict__ out4,
     float* __restrict__ outf, unsigned sn) {
    __shared__ SmemAll sm;
    unsigned bid = blockIdx.x;
    unsigned NB  = gridDim.x;
    int t = threadIdx.x;

    // ===== Phase 1: radix selects (blocks 0..95) + copy chunks 0..399 =====
    if (bid < 96u) {
        for (unsigned task = bid; task < 96u; task += NB) doSelect(sm.sel, x, (int)task);
    } else {
        for (unsigned c = bid - 96u; c < CH_P1; c += NB - 96u) copy8(in4, out4, c);
    }
    gridSync(NB);

    // ===== Phase 2: analytics (blocks 0..7) + copy chunks 400..549 =====
    if (bid < 8u) {
        doKB(sm.kb, w1, (int)bid);
    } else {
        for (unsigned c = CH_P1 + (bid - 8u); c < CH_P1 + CH_P2; c += NB - 8u)
            copy8(in4, out4, c);
    }
    gridSync(NB);

    // ===== Phase 3: matvec+row0 (0..191), rank (192..223), copy 550..587 =====
    for (unsigned task = bid; task < 224u; task += NB) {
        __syncthreads();                           // smem reuse across tasks
        if (task < 192u) {
            int b    = (int)(task / 24u);
            int tile = (int)(task - (unsigned)b * 24u);
            for (int k = t; k < GCNH; k += 256) sm.mv.wk[k] = g_wk[b*GCNH + k];
            __syncthreads();
            int col = tile * 32 + (t & 31);
            int jq  = t >> 5;
            const float* w2p = w2 + col;
            float acc = 0.f;
            int j0 = jq * 64;
            #pragma unroll 8
            for (int j = 0; j < 64; j++) acc += sm.mv.wk[j0 + j] * w2p[(size_t)(j0 + j) * D_];
            sm.mv.partr[t] = acc;
            __syncthreads();
            if (t < 32) {
                float o = 0.f;
                #pragma unroll
                for (int q = 0; q < 8; q++) o += sm.mv.partr[t + q*32];
                int c = tile * 32 + t;
                float st = (o > 0.f) ? o : 0.2f * o;
                unsigned idx = (unsigned)b * 602880u + (unsigned)c;   // row 0 of batch b
                outf[idx] = hsf[idx] + st;
            }
        } else {
            unsigned idx = task - 192u;            // 0..31
            int b    = (int)(idx >> 2);
            int part = (int)(idx & 3u);
            for (int s = t; s < S_; s += 256) sm.rk.kk[s] = g_key[b*S_ + s];
            __syncthreads();
            if (t < 196) {
                int s = part * 196 + t;
                int ks = sm.rk.kk[s];
                int r = 0;
                #pragma unroll 8
                for (int u = 0; u < S_; u++) r += (sm.rk.kk[u] > ks);
                if (r < (int)sn) g_pidx[b*S_ + r] = s + 1;
            }
        }
    }
    if (bid >= 224u) {
        for (unsigned c = CH_P1 + CH_P2 + (bid - 224u); c < NCHUNK; c += NB - 224u)
            copy8(in4, out4, c);
    }
    gridSync(NB);

    // ===== Phase 4: gather selected rows =====
    unsigned ng = sn * 8u * ROWF4;
    for (unsigned j = bid * 256u + (unsigned)t; j < ng; j += NB * 256u) {
        unsigned rr = j / ROWF4;                   // b*sn + jj
        unsigned k4 = j - rr * ROWF4;
        unsigned b  = rr / sn;
        unsigned jj = rr - b * sn;
        unsigned row = (unsigned)g_pidx[b*S_ + jj];
        out4[NHS4 + j] = in4[(b*785u + row)*ROWF4 + k4];
    }
}

// ---------------- launch ----------------
extern "C" void kernel_launch(void* const* d_in, const int* in_sizes, int n_in,
                              void* d_out, int out_size) {
    const float* hs = (const float*)d_in[0];
    const float* x  = (const float*)d_in[1];
    const float* w1 = (const float*)d_in[2];
    const float* w2 = (const float*)d_in[3];
    (void)in_sizes; (void)n_in;

    int sn = out_size / (B_ * D_) - NTOK;     // selected rows per batch
    if (sn < 1) sn = 1;
    if (sn > S_) sn = S_;

    int nsm = 0;
    if (cudaDeviceGetAttribute(&nsm, cudaDevAttrMultiProcessorCount, 0) != cudaSuccess || nsm <= 0)
        nsm = 64;
    unsigned nblk = (unsigned)nsm * 4u;        // __launch_bounds__(256,4) guarantees residency

    kAll<<<nblk, 256>>>(x, w1, w2, hs, (const float4*)hs, (float4*)d_out,
                        (float*)d_out, (unsigned)sn);
}

// round 12
// speedup vs baseline: 1.1197x; 1.1197x over previous
#include <cuda_runtime.h>
#include <math.h>

#define B_  8
#define C_  12
#define S_  784
#define NTOK 785
#define D_  768
#define HH  28
#define PATCH 84
#define GCNH 512

#define ROWF4    192u          /* 768 floats per row */
#define BATF4    150720u       /* 785*192 per batch  */
#define NHS4     1205760u      /* 8*785*192          */
#define NCHUNK   588u          /* (8*784*192)/2048   */
#define CH_K1    294u
#define CH_K2    147u          /* k3 gets the last 147 */

// ---------------- scratch (no allocation allowed) ----------------
// amap/selflag layout: [b][s][c], c fastest (read-optimized for doKB)
__device__ float         g_amap[B_*S_*C_];
__device__ unsigned char g_selflag[B_*S_*C_];
__device__ float         g_wk[B_*GCNH];
__device__ int           g_pidx[B_*S_];
__device__ int           g_key[B_*S_];

// monotone float->uint: a > b <=> f2u(a) > f2u(b)
__device__ __forceinline__ unsigned f2u(float f) {
    unsigned u = __float_as_uint(f);
    return (u & 0x80000000u) ? ~u : (u | 0x80000000u);
}

// ---- bulk copy of rows 1..784 (chunk = 2048 float4, ILP=8) ------------------
__device__ __forceinline__ void copy8(const float4* __restrict__ in4,
                                      float4* __restrict__ out4, unsigned chunk) {
    unsigned m0 = chunk * 2048u + threadIdx.x;
    unsigned src[8]; float4 v[8];
    #pragma unroll
    for (int e = 0; e < 8; e++) {
        unsigned m = m0 + (unsigned)e * 256u;       // m in [0, 8*784*192)
        unsigned b = m / 150528u;                   // 784*192 per batch
        src[e] = m + (b + 1u) * ROWF4;              // skip row 0 of each batch
    }
    #pragma unroll
    for (int e = 0; e < 8; e++) v[e] = in4[src[e]];
    #pragma unroll
    for (int e = 0; e < 8; e++) out4[src[e]] = v[e];
}

// ================= k1: radix selects (0..95) + copy (96..) ===================
__global__ void __launch_bounds__(256) k1(const float* __restrict__ x,
                                          const float4* __restrict__ in4,
                                          float4* __restrict__ out4) {
#if __CUDA_ARCH__ >= 900
    cudaTriggerProgrammaticLaunchCompletion();
#endif
    if (blockIdx.x >= 96u) {
        copy8(in4, out4, blockIdx.x - 96u);        // chunks 0..293
        return;
    }
    int bc = blockIdx.x;
    int t  = threadIdx.x;
    unsigned lane = t & 31;
    int wid = t >> 5;
    __shared__ float    sc[S_];
    __shared__ unsigned key[S_];
    __shared__ int      hist[256];
    __shared__ int      wtot[8];
    __shared__ unsigned s_prefix;
    __shared__ int      s_k;

    const float* base = x + (size_t)bc * NTOK * NTOK + 1;   // x[b,c,0,1:]
    for (int s = t; s < S_; s += 256) {
        float v = base[s];
        sc[s]  = v;
        key[s] = f2u(v);
    }
    if (t == 0) { s_prefix = 0u; s_k = PATCH; }

    #pragma unroll
    for (int p = 0; p < 4; p++) {
        int shift = 24 - 8 * p;
        hist[t] = 0;
        __syncthreads();
        unsigned pref = s_prefix;
        int      k    = s_k;
        for (int s = t; s < S_; s += 256) {
            unsigned kk = key[s];
            bool cand = (p == 0) || (((kk ^ pref) >> (shift + 8)) == 0u);
            if (cand) atomicAdd(&hist[(kk >> shift) & 255], 1);
        }
        __syncthreads();
        int v = hist[t];
        int xsum = v;
        #pragma unroll
        for (int off = 1; off < 32; off <<= 1) {
            int y = __shfl_down_sync(0xFFFFFFFFu, xsum, off);
            if (lane + off < 32) xsum += y;
        }
        if (lane == 0) wtot[wid] = xsum;
        __syncthreads();
        int addhi = 0;
        for (int ww = wid + 1; ww < 8; ww++) addhi += wtot[ww];
        int suffix = xsum + addhi;
        int above  = suffix - v;
        if (suffix >= k && above < k) {            // exactly one thread matches
            s_prefix = pref | ((unsigned)t << shift);
            s_k      = k - above;
        }
    }
    __syncthreads();

    unsigned T  = s_prefix;
    int     neq = s_k;
    int b = bc / C_, c = bc - b * C_;
    unsigned baseo = (unsigned)(b * S_) * (unsigned)C_ + (unsigned)c;
    for (int s = t; s < S_; s += 256) {
        unsigned kk = key[s];
        bool sel;
        if (kk > T) sel = true;
        else if (kk == T) {
            int eq = 0;
            for (int u = 0; u < s; u++) eq += (key[u] == T);
            sel = eq < neq;
        } else sel = false;
        float v = sc[s];
        g_amap[baseo + (unsigned)s * C_]    = sel ? v : 0.7f * v;
        g_selflag[baseo + (unsigned)s * C_] = sel ? 1 : 0;
    }
}

// ================= k2: analytics (0..7, PDL-sync) + copy (8..) ===============
__global__ void __launch_bounds__(256) k2(const float* __restrict__ w1,
                                          const float4* __restrict__ in4,
                                          float4* __restrict__ out4) {
#if __CUDA_ARCH__ >= 900
    cudaTriggerProgrammaticLaunchCompletion();
#endif
    if (blockIdx.x >= 8u) {
        copy8(in4, out4, CH_K1 + (blockIdx.x - 8u));   // chunks 294..440
        return;
    }
#if __CUDA_ARCH__ >= 900
    cudaGridDependencySynchronize();               // wait for k1's amap/selflag
#endif
    int b = blockIdx.x;
    int t = threadIdx.x;
    unsigned lane = t & 31;
    int wid = t >> 5;
    const int NT = 256;
    __shared__ float  pw[S_];
    __shared__ float  binm[S_];
    __shared__ float  cnt[S_];
    __shared__ float  wsum[8];
    __shared__ unsigned long long wkey[8];
    __shared__ float4 wq[8];
    __shared__ float  s_mean, s_panchor;
    __shared__ float4 s_q;
    __shared__ int    s_anchor;

    const float4* ab4 = (const float4*)(g_amap + (size_t)b * S_ * C_);
    float part = 0.f;
    for (int s = t; s < S_; s += NT) {
        float4 a0 = ab4[s*3], a1 = ab4[s*3+1], a2 = ab4[s*3+2];
        float smv = a0.x+a0.y+a0.z+a0.w + a1.x+a1.y+a1.z+a1.w + a2.x+a2.y+a2.z+a2.w;
        binm[s] = smv;
        pw[s]   = smv * (1.f/12.f);
        part += smv;
    }
    #pragma unroll
    for (int off = 16; off > 0; off >>= 1) part += __shfl_down_sync(0xFFFFFFFFu, part, off);
    if (lane == 0) wsum[wid] = part;
    __syncthreads();
    if (t < 8) {
        float v = wsum[t];
        #pragma unroll
        for (int off = 4; off > 0; off >>= 1) v += __shfl_down_sync(0xFFu, v, off);
        if (t == 0) s_mean = v / (float)S_;
    }
    __syncthreads();
    float mean = s_mean;
    for (int s = t; s < S_; s += NT) binm[s] = (binm[s] > mean) ? 1.f : 0.f;

    // anchor = argmax binm*pw (first index wins), u64 key, -0.0 canonicalized
    unsigned long long akey = 0ull;
    for (int s = t; s < S_; s += NT) {
        float v = binm[s] * pw[s];
        unsigned uv = __float_as_uint(v);
        if (uv == 0x80000000u) uv = 0u;
        unsigned fv = (uv & 0x80000000u) ? ~uv : (uv | 0x80000000u);
        unsigned long long k = ((unsigned long long)fv << 32) | (unsigned long long)(0xFFFFFFFFu - (unsigned)s);
        if (k > akey) akey = k;
    }
    #pragma unroll
    for (int off = 16; off > 0; off >>= 1) {
        unsigned long long o = __shfl_down_sync(0xFFFFFFFFu, akey, off);
        if (o > akey) akey = o;
    }
    if (lane == 0) wkey[wid] = akey;
    __syncthreads();
    if (t < 8) {
        unsigned long long k = wkey[t];
        #pragma unroll
        for (int off = 4; off > 0; off >>= 1) {
            unsigned long long o = __shfl_down_sync(0xFFu, k, off);
            if (o > k) k = o;
        }
        if (t == 0) {
            int a = (int)(0xFFFFFFFFu - (unsigned)(k & 0xFFFFFFFFull));
            s_anchor = a;
            s_panchor = pw[a];
        }
    }
    __syncthreads();
    int anchor = s_anchor;
    float ai = (float)(anchor / HH), aj = (float)(anchor % HH);

    float4 acc4 = make_float4(0.f, 0.f, 0.f, 0.f);
    for (int s = t; s < S_; s += NT) {
        float rx = ((float)(s / HH) - ai) / 28.0f;
        float ry = ((float)(s % HH) - aj) / 28.0f;
        float dist = sqrtf(rx*rx + ry*ry);
        float ang  = (atan2f(ry, rx) / (float)M_PI + 1.f) * 0.5f;
        float p = pw[s];
        acc4.x += p * dist;
        acc4.y += p * ang;
        if (p > 0.f) acc4.z += p*p; else if (p < 0.f) acc4.w += p*p;
    }
    #pragma unroll
    for (int off = 16; off > 0; off >>= 1) {
        acc4.x += __shfl_down_sync(0xFFFFFFFFu, acc4.x, off);
        acc4.y += __shfl_down_sync(0xFFFFFFFFu, acc4.y, off);
        acc4.z += __shfl_down_sync(0xFFFFFFFFu, acc4.z, off);
        acc4.w += __shfl_down_sync(0xFFFFFFFFu, acc4.w, off);
    }
    if (lane == 0) wq[wid] = acc4;
    __syncthreads();
    if (t < 8) {
        float4 a = wq[t];
        #pragma unroll
        for (int off = 4; off > 0; off >>= 1) {
            a.x += __shfl_down_sync(0xFFu, a.x, off);
            a.y += __shfl_down_sync(0xFFu, a.y, off);
            a.z += __shfl_down_sync(0xFFu, a.z, off);
            a.w += __shfl_down_sync(0xFFu, a.w, off);
        }
        if (t == 0) s_q = a;
    }
    __syncthreads();
    float Q0 = s_q.x, Q1 = s_q.y, AP = s_q.z, AM = s_q.w;
    float pa = s_panchor;

    for (int k = t; k < GCNH; k += NT) {
        float v = Q0 * w1[k] + Q1 * w1[GCNH + k];
        float wv = (v > 0.f) ? v * AP : ((v < 0.f) ? v * AM : 0.f);
        g_wk[b*GCNH + k] = pa * wv;
    }

    // count via packed selflag + dp4a
    const unsigned* sf = (const unsigned*)(g_selflag + (size_t)b * S_ * C_);
    for (int s = t; s < S_; s += NT) {
        int acc = __dp4a((int)sf[s*3+2], 0x01010101,
                  __dp4a((int)sf[s*3+1], 0x01010101,
                  __dp4a((int)sf[s*3+0], 0x01010101, 0)));
        cnt[s] = (float)acc;
    }
    __syncthreads();
    for (int s = t; s < S_; s += NT) {
        int li = s / HH, lj = s % HH;
        float acc = 0.f;
        #pragma unroll
        for (int di = -1; di <= 1; di++) {
            #pragma unroll
            for (int dj = -1; dj <= 1; dj++) {
                int ni = li + di, nj = lj + dj;
                if (ni >= 0 && ni < HH && nj >= 0 && nj < HH) {
                    float kw = ((di == 0) ? 2.f : 1.f) * ((dj == 0) ? 2.f : 1.f);
                    acc += kw * cnt[ni*HH + nj];
                }
            }
        }
        g_key[b*S_ + s] = (int)acc * 1024 + (1023 - s);
    }
}

// ======= k3: matvec+row0 (0..191), rank (192..223) [PDL-sync] + copy =========
__global__ void __launch_bounds__(256) k3(const float* __restrict__ w2, int sn,
                                          const float* __restrict__ hsf,
                                          float* __restrict__ outf,
                                          const float4* __restrict__ in4,
                                          float4* __restrict__ out4) {
#if __CUDA_ARCH__ >= 900
    cudaTriggerProgrammaticLaunchCompletion();
#endif
    int blk = blockIdx.x;
    int t   = threadIdx.x;
    if (blk >= 224) {
        copy8(in4, out4, CH_K1 + CH_K2 + (unsigned)(blk - 224));  // 441..587
        return;
    }
#if __CUDA_ARCH__ >= 900
    cudaGridDependencySynchronize();               // wait for k2's g_wk/g_key
#endif
    if (blk < 192) {
        int b    = blk / 24;
        int tile = blk - b * 24;
        __shared__ float wk[GCNH];
        __shared__ float partr[256];
        for (int k = t; k < GCNH; k += 256) wk[k] = g_wk[b*GCNH + k];
        __syncthreads();
        int col = tile * 32 + (t & 31);
        int jq  = t >> 5;
        const float* w2p = w2 + col;
        float acc = 0.f;
        int j0 = jq * 64;
        #pragma unroll 8
        for (int j = 0; j < 64; j++) acc += wk[j0 + j] * w2p[(size_t)(j0 + j) * D_];
        partr[t] = acc;
        __syncthreads();
        if (t < 32) {
            float o = 0.f;
            #pragma unroll
            for (int q = 0; q < 8; q++) o += partr[t + q*32];
            int c = tile * 32 + t;
            float st = (o > 0.f) ? o : 0.2f * o;
            unsigned idx = (unsigned)b * 602880u + (unsigned)c;   // row 0 of batch b
            outf[idx] = hsf[idx] + st;
        }
    } else {
        unsigned idx = (unsigned)(blk - 192);      // 0..31
        int b    = (int)(idx >> 2);
        int part = (int)(idx & 3u);
        __shared__ int kk[S_];
        for (int s = t; s < S_; s += 256) kk[s] = g_key[b*S_ + s];
        __syncthreads();
        if (t < 196) {
            int s = part * 196 + t;
            int ks = kk[s];
            int r = 0;
            #pragma unroll 8
            for (int u = 0; u < S_; u++) r += (kk[u] > ks);
            if (r < sn) g_pidx[b*S_ + r] = s + 1;
        }
    }
}

// ================= k4: gather selected rows (PDL-sync) =======================
__global__ void __launch_bounds__(256) k4(const float4* __restrict__ in4,
                                          float4* __restrict__ out4,
                                          unsigned sn, unsigned ng) {
#if __CUDA_ARCH__ >= 900
    cudaGridDependencySynchronize();               // wait for k3's g_pidx
#endif
    unsigned j = blockIdx.x * 256u + threadIdx.x;
    if (j >= ng) return;
    unsigned rr = j / ROWF4;                       // b*sn + jj
    unsigned k4i = j - rr * ROWF4;
    unsigned b  = rr / sn;
    unsigned jj = rr - b * sn;
    unsigned row = (unsigned)g_pidx[b*S_ + jj];
    out4[NHS4 + j] = in4[(b*785u + row)*ROWF4 + k4i];
}

// ---------------- launch (PDL chain) ----------------
template <typename K, typename... Args>
static void launchPDL(K kern, unsigned grid, Args... args) {
    cudaLaunchConfig_t cfg = {};
    cfg.gridDim  = dim3(grid, 1, 1);
    cfg.blockDim = dim3(256, 1, 1);
    cfg.stream   = 0;
    cudaLaunchAttribute at[1];
    at[0].id = cudaLaunchAttributeProgrammaticStreamSerialization;
    at[0].val.programmaticStreamSerializationAllowed = 1;
    cfg.attrs = at;
    cfg.numAttrs = 1;
    cudaLaunchKernelEx(&cfg, kern, args...);
}

extern "C" void kernel_launch(void* const* d_in, const int* in_sizes, int n_in,
                              void* d_out, int out_size) {
    const float* hs = (const float*)d_in[0];
    const float* x  = (const float*)d_in[1];
    const float* w1 = (const float*)d_in[2];
    const float* w2 = (const float*)d_in[3];
    (void)in_sizes; (void)n_in;

    int sn = out_size / (B_ * D_) - NTOK;          // selected rows per batch
    if (sn < 1) sn = 1;
    if (sn > S_) sn = S_;

    const float4* in4 = (const float4*)hs;
    float4* out4 = (float4*)d_out;

    k1<<<96u + CH_K1, 256>>>(x, in4, out4);
    launchPDL(k2, 8u + CH_K2, w1, in4, out4);
    launchPDL(k3, 224u + (NCHUNK - CH_K1 - CH_K2), w2, sn, hs, (float*)d_out, in4, out4);
    unsigned ng = (unsigned)(B_ * sn) * ROWF4;
    launchPDL(k4, (ng + 255u) / 256u, in4, out4, (unsigned)sn, ng);
}